// round 4
// baseline (speedup 1.0000x reference)
#include <cuda_runtime.h>

#define BSZ   1024
#define TLEN  64
#define SDIM  30
#define DDIM  200
#define HDIM  200
#define EDIM  1024
#define ADIM  6

typedef unsigned long long ull;

// ---------------------------------------------------------------------------
// Device scratch
// ---------------------------------------------------------------------------
__device__ float g_eo[(size_t)BSZ * TLEN * HDIM];   // embed @ w_obs1[200:] + b_obs1

// Column-pair packed weights: element (..., kq, c2) = 8 floats =
// [col 2*c2: k=4kq..4kq+3][col 2*c2+1: k=4kq..4kq+3]
__device__ float4 g_gru8[60000];   // [st 0..5][kq 0..49][c2 0..99] * 2 float4
__device__ float4 g_p48[20000];    // [mat 0..1][kq 0..49][c2 0..99] * 2  (img2, obs1d)
__device__ float4 g_i18[1800];     // [kq 0..8][c2 0..99] * 2              (img1, K=36)
__device__ float4 g_h8[6000];      // [h 0..3][kq 0..49][s2 0..14] * 2     (heads)

// ---------------------------------------------------------------------------
// Helpers
// ---------------------------------------------------------------------------
__device__ __forceinline__ ull fma2(ull a, ull b, ull c) {
    ull d;
    asm("fma.rn.f32x2 %0, %1, %2, %3;" : "=l"(d) : "l"(a), "l"(b), "l"(c));
    return d;
}
__device__ __forceinline__ float sum2(ull a) {
    float2 f;
    asm("mov.b64 {%0, %1}, %2;" : "=f"(f.x), "=f"(f.y) : "l"(a));
    return f.x + f.y;
}
__device__ __forceinline__ ulonglong2 ldg2(const float4* p) {
    return __ldg(reinterpret_cast<const ulonglong2*>(p));
}
__device__ __forceinline__ ulonglong2 lds2(const float* p) {
    return *reinterpret_cast<const ulonglong2*>(p);
}
__device__ __forceinline__ float elu1(float v) {
    return v > 0.f ? v : (__expf(v) - 1.f);
}
__device__ __forceinline__ float softplus1(float x) {
    return fmaxf(x, 0.f) + log1pf(__expf(-fabsf(x)));
}
__device__ __forceinline__ float sigmoid1(float x) {
    return 1.f / (1.f + __expf(-x));
}

// ---------------------------------------------------------------------------
// Repack into column-pair quad layouts
// ---------------------------------------------------------------------------
__device__ __forceinline__ void repack_one(int i,
                                           const float* __restrict__ w_img1,
                                           const float* __restrict__ gru_w,
                                           const float* __restrict__ gru_u,
                                           const float* __restrict__ w_img2,
                                           const float* __restrict__ w_obs1,
                                           const float* __restrict__ w_omean,
                                           const float* __restrict__ w_ostd,
                                           const float* __restrict__ w_imean,
                                           const float* __restrict__ w_istd) {
    if (i < 240000) {                       // GRU: st 0..5 = Wz,Wr,Wh,Uz,Ur,Uh
        int e = i % 8, q = i / 8;
        int c2 = q % 100, kq = (q / 100) % 50, st = q / 5000;
        int col = 2 * c2 + (e >> 2), k = 4 * kq + (e & 3);
        float v = (st < 3) ? gru_w[k * 600 + st * 200 + col]
                           : gru_u[k * 600 + (st - 3) * 200 + col];
        ((float*)g_gru8)[i] = v;
    } else if (i < 320000) {                // mat0=img2, mat1=obs1d
        int j = i - 240000;
        int e = j % 8, q = j / 8;
        int c2 = q % 100, kq = (q / 100) % 50, mat = q / 5000;
        int col = 2 * c2 + (e >> 2), k = 4 * kq + (e & 3);
        ((float*)g_p48)[j] = (mat == 0) ? w_img2[k * 200 + col]
                                        : w_obs1[k * 200 + col];
    } else if (i < 327200) {                // img1, K=36
        int j = i - 320000;
        int e = j % 8, q = j / 8;
        int c2 = q % 100, kq = q / 100;
        int col = 2 * c2 + (e >> 2), k = 4 * kq + (e & 3);
        ((float*)g_i18)[j] = w_img1[k * 200 + col];
    } else if (i < 351200) {                // heads
        int j = i - 327200;
        int e = j % 8, q = j / 8;
        int s2 = q % 15, kq = (q / 15) % 50, h = q / 750;
        int s = 2 * s2 + (e >> 2), k = 4 * kq + (e & 3);
        const float* src = (h == 0) ? w_omean : (h == 1) ? w_ostd
                         : (h == 2) ? w_imean : w_istd;
        ((float*)g_h8)[j] = src[k * 30 + s];
    }
}

// ---------------------------------------------------------------------------
// Kernel 1: repack + eo GEMM (register double-buffered prefetch)
// ---------------------------------------------------------------------------
__global__ __launch_bounds__(320, 1)
void eo_gemm_kernel(const float* __restrict__ embed,
                    const float* __restrict__ w_obs1,
                    const float* __restrict__ b_obs1,
                    const float* __restrict__ w_img1,
                    const float* __restrict__ gru_w,
                    const float* __restrict__ gru_u,
                    const float* __restrict__ w_img2,
                    const float* __restrict__ w_omean,
                    const float* __restrict__ w_ostd,
                    const float* __restrict__ w_imean,
                    const float* __restrict__ w_istd) {
    for (int i = blockIdx.x * 320 + threadIdx.x; i < 351200; i += 1024 * 320) {
        repack_one(i, w_img1, gru_w, gru_u, w_img2, w_obs1,
                   w_omean, w_ostd, w_imean, w_istd);
    }

    __shared__ __align__(16) float as_f[64 * 32];
    __shared__ __align__(16) float ws_f[32 * 200];
    const ull* as_u = (const ull*)as_f;
    const ull* ws_u = (const ull*)ws_f;

    const int tid = threadIdx.x;
    const int tx = tid % 40;
    const int ty = tid / 40;
    const int m0 = blockIdx.x * 64;

    ull acc[8][5];
#pragma unroll
    for (int r = 0; r < 8; r++)
#pragma unroll
        for (int j = 0; j < 5; j++) acc[r][j] = 0ull;

    float4 aP[2];
    float4 wP[5];
    const bool aPred = (tid < 256);

    {
        if (aPred) {
#pragma unroll
            for (int p = 0; p < 2; p++) {
                int q = tid + 256 * p;
                int r = q >> 3, qq = q & 7;
                aP[p] = *reinterpret_cast<const float4*>(
                    embed + (size_t)(m0 + r) * 1024 + qq * 4);
            }
        }
#pragma unroll
        for (int p = 0; p < 5; p++) {
            int q = tid + 320 * p;
            int k = q / 50, c4 = (q % 50) * 4;
            wP[p] = *reinterpret_cast<const float4*>(
                w_obs1 + (size_t)(200 + k) * 200 + c4);
        }
    }

    for (int chunk = 0; chunk < 32; chunk++) {
        __syncthreads();
        if (aPred) {
#pragma unroll
            for (int p = 0; p < 2; p++) {
                int q = tid + 256 * p;
                int r = q >> 3, qq = q & 7;
                *reinterpret_cast<float4*>(as_f + r * 32 + qq * 4) = aP[p];
            }
        }
#pragma unroll
        for (int p = 0; p < 5; p++) {
            int q = tid + 320 * p;
            int k = q / 50, c4 = (q % 50) * 4;
            float vv[4] = {wP[p].x, wP[p].y, wP[p].z, wP[p].w};
#pragma unroll
            for (int j = 0; j < 4; j++)
                ws_f[((k >> 1) * 200 + c4 + j) * 2 + (k & 1)] = vv[j];
        }
        __syncthreads();

        if (chunk < 31) {
            int k0 = (chunk + 1) * 32;
            if (aPred) {
#pragma unroll
                for (int p = 0; p < 2; p++) {
                    int q = tid + 256 * p;
                    int r = q >> 3, qq = q & 7;
                    aP[p] = *reinterpret_cast<const float4*>(
                        embed + (size_t)(m0 + r) * 1024 + k0 + qq * 4);
                }
            }
#pragma unroll
            for (int p = 0; p < 5; p++) {
                int q = tid + 320 * p;
                int k = q / 50, c4 = (q % 50) * 4;
                wP[p] = *reinterpret_cast<const float4*>(
                    w_obs1 + (size_t)(200 + k0 + k) * 200 + c4);
            }
        }

#pragma unroll
        for (int kp = 0; kp < 16; kp++) {
            ull wv[5];
#pragma unroll
            for (int j = 0; j < 5; j++) wv[j] = ws_u[kp * 200 + tx * 5 + j];
#pragma unroll
            for (int r = 0; r < 8; r++) {
                ull av = as_u[(ty * 8 + r) * 16 + kp];
#pragma unroll
                for (int j = 0; j < 5; j++) acc[r][j] = fma2(av, wv[j], acc[r][j]);
            }
        }
    }

#pragma unroll
    for (int r = 0; r < 8; r++) {
        int m = m0 + ty * 8 + r;
#pragma unroll
        for (int j = 0; j < 5; j++) {
            int cc = tx * 5 + j;
            g_eo[(size_t)m * 200 + cc] = sum2(acc[r][j]) + b_obs1[cc];
        }
    }
}

// ---------------------------------------------------------------------------
// Kernel 2: persistent recurrent kernel — gate-split + 2-cols/thread.
// 128 CTAs x 8 batch rows, 800 threads.
// ---------------------------------------------------------------------------
__global__ __launch_bounds__(800, 1)
void rssm_recur_kernel(const float* __restrict__ action,
                       const float* __restrict__ noise_prior,
                       const float* __restrict__ noise_post,
                       const float* __restrict__ b_img1,
                       const float* __restrict__ gru_b,
                       const float* __restrict__ gru_rb,
                       const float* __restrict__ b_img2,
                       const float* __restrict__ b_imean,
                       const float* __restrict__ b_istd,
                       const float* __restrict__ b_omean,
                       const float* __restrict__ b_ostd,
                       float* __restrict__ out) {
    __shared__ __align__(16) float sm[20608];
    float* s_in = sm;            // [8][40]   stoch(30)+action(6)+pad(4)   320
    float* det0 = sm + 320;      // [8][200]                              1600
    float* det1 = sm + 1920;     // [8][200]                              1600
    float* s_x  = sm + 3520;     // [8][200]  img1 out, later x2          1600
    float* s_xo = sm + 5120;     // [8][200]                              1600
    float* s_eo = sm + 6720;     // [8][200]                              1600
    float* s_hd = sm + 8320;     // [4][8][30]                             960
    float* s_g  = sm + 9280;     // [6][8][200] GRU stream pre-acts       9600
    float* s_b1 = sm + 18880;    // [200]
    float* s_b2 = sm + 19080;    // [200]
    float* s_gb = sm + 19280;    // [6][200]
    float* s_hb = sm + 20480;    // [4][30]

    const int tid = threadIdx.x;
    const int b0 = blockIdx.x * 8;

    // ---- init: biases to smem, carry zeros, action[0] ----
    if (tid < 200) {
        s_b1[tid] = b_img1[tid];
        s_b2[tid] = b_img2[tid];
    }
    for (int i = tid; i < 1200; i += 800) {
        int st = i / 200, cc = i % 200;
        s_gb[i] = (st < 3) ? gru_b[st * 200 + cc] : gru_rb[(st - 3) * 200 + cc];
    }
    if (tid < 120) {
        int h = tid / 30, s = tid % 30;
        s_hb[tid] = (h == 0) ? b_omean[s] : (h == 1) ? b_ostd[s]
                  : (h == 2) ? b_imean[s] : b_istd[s];
    }
    for (int i = tid; i < 320; i += 800) s_in[i] = 0.f;
    for (int i = tid; i < 1600; i += 800) det0[i] = 0.f;
    if (tid < 48) {
        int r = tid / 6, j = tid % 6;
        s_in[r * 40 + 30 + j] = action[(size_t)(b0 + r) * (TLEN * ADIM) + j];
    }
    float* pd = det0;
    float* pn = det1;
    __syncthreads();

    for (int t = 0; t < TLEN; ++t) {
        // ====== P1: x = elu([stoch,action]@W1 + b)  |  eo loads =============
        if (tid < 200) {
            const int rh = tid / 100, c2 = tid % 100;
            const float4* wp = g_i18 + c2 * 2;
            ull a0[4], a1[4];
#pragma unroll
            for (int j = 0; j < 4; j++) { a0[j] = 0; a1[j] = 0; }
#pragma unroll
            for (int kq = 0; kq < 9; kq++) {
                ulonglong2 w0 = ldg2(wp + kq * 200);
                ulonglong2 w1 = ldg2(wp + kq * 200 + 1);
#pragma unroll
                for (int j = 0; j < 4; j++) {
                    ulonglong2 v = lds2(s_in + (rh * 4 + j) * 40 + 4 * kq);
                    a0[j] = fma2(v.x, w0.x, a0[j]);
                    a0[j] = fma2(v.y, w0.y, a0[j]);
                    a1[j] = fma2(v.x, w1.x, a1[j]);
                    a1[j] = fma2(v.y, w1.y, a1[j]);
                }
            }
            float bb0 = s_b1[2 * c2], bb1 = s_b1[2 * c2 + 1];
#pragma unroll
            for (int j = 0; j < 4; j++) {
                int rr = rh * 4 + j;
                s_x[rr * 200 + 2 * c2]     = elu1(sum2(a0[j]) + bb0);
                s_x[rr * 200 + 2 * c2 + 1] = elu1(sum2(a1[j]) + bb1);
            }
        } else if (tid >= 600) {
            int t2 = tid - 600;
#pragma unroll
            for (int i = 0; i < 8; i++) {
                int e = t2 + 200 * i;
                int r = e / 200, cc = e - r * 200;
                s_eo[e] = __ldg(&g_eo[((size_t)(b0 + r) * TLEN + t) * 200 + cc]);
            }
        }
        __syncthreads();

        // ====== P2: 6 GRU streams, 2 cols/thread =============================
        if (tid < 600) {
            const int st = tid / 100, c2 = tid % 100;
            const float* src = (st < 3) ? s_x : pd;
            const float4* wp = g_gru8 + (st * 5000 + c2) * 2;
            ull a0[8], a1[8];
#pragma unroll
            for (int r = 0; r < 8; r++) { a0[r] = 0; a1[r] = 0; }
#pragma unroll 2
            for (int kq = 0; kq < 50; kq++) {
                ulonglong2 w0 = ldg2(wp + kq * 200);
                ulonglong2 w1 = ldg2(wp + kq * 200 + 1);
#pragma unroll
                for (int r = 0; r < 8; r++) {
                    ulonglong2 v = lds2(src + r * 200 + 4 * kq);
                    a0[r] = fma2(v.x, w0.x, a0[r]);
                    a0[r] = fma2(v.y, w0.y, a0[r]);
                    a1[r] = fma2(v.x, w1.x, a1[r]);
                    a1[r] = fma2(v.y, w1.y, a1[r]);
                }
            }
            float gb0 = s_gb[st * 200 + 2 * c2];
            float gb1 = s_gb[st * 200 + 2 * c2 + 1];
#pragma unroll
            for (int r = 0; r < 8; r++) {
                float2 o;
                o.x = sum2(a0[r]) + gb0;
                o.y = sum2(a1[r]) + gb1;
                *reinterpret_cast<float2*>(s_g + st * 1600 + r * 200 + 2 * c2) = o;
            }
        }
        __syncthreads();

        // ====== P3: gates, deter_n ==========================================
#pragma unroll
        for (int i = 0; i < 2; i++) {
            int idx = tid + 800 * i;
            float z  = sigmoid1(s_g[idx] + s_g[4800 + idx]);
            float rg = sigmoid1(s_g[1600 + idx] + s_g[6400 + idx]);
            float a  = s_g[3200 + idx] + rg * s_g[8000 + idx];
            float e2 = __expf(2.f * a);
            float th = 1.f - 2.f / (e2 + 1.f);
            float dn = z * pd[idx] + (1.f - z) * th;
            pn[idx] = dn;
            int r = idx / 200, cc = idx - r * 200;
            float* orow = out + ((size_t)(b0 + r) * TLEN + t) * 580;
            orow[90 + cc]  = dn;
            orow[380 + cc] = dn;
        }
        __syncthreads();

        // ====== P4: x2 / xo, 2 cols x 4 rows per thread =====================
        if (tid < 400) {
            const int mat = tid / 200;
            const int rem = tid - mat * 200;
            const int rh = rem / 100, c2 = rem % 100;
            const float4* wp = g_p48 + (mat * 5000 + c2) * 2;
            const float* db = pn + rh * 4 * 200;
            ull a0[4], a1[4];
#pragma unroll
            for (int j = 0; j < 4; j++) { a0[j] = 0; a1[j] = 0; }
#pragma unroll 2
            for (int kq = 0; kq < 50; kq++) {
                ulonglong2 w0 = ldg2(wp + kq * 200);
                ulonglong2 w1 = ldg2(wp + kq * 200 + 1);
#pragma unroll
                for (int j = 0; j < 4; j++) {
                    ulonglong2 v = lds2(db + j * 200 + 4 * kq);
                    a0[j] = fma2(v.x, w0.x, a0[j]);
                    a0[j] = fma2(v.y, w0.y, a0[j]);
                    a1[j] = fma2(v.x, w1.x, a1[j]);
                    a1[j] = fma2(v.y, w1.y, a1[j]);
                }
            }
            int cc = 2 * c2;
            if (mat == 0) {
                float bb0 = s_b2[cc], bb1 = s_b2[cc + 1];
#pragma unroll
                for (int j = 0; j < 4; j++) {
                    int rr = rh * 4 + j;
                    s_x[rr * 200 + cc]     = elu1(sum2(a0[j]) + bb0);
                    s_x[rr * 200 + cc + 1] = elu1(sum2(a1[j]) + bb1);
                }
            } else {
#pragma unroll
                for (int j = 0; j < 4; j++) {
                    int rr = rh * 4 + j;
                    s_xo[rr * 200 + cc]     = elu1(sum2(a0[j]) + s_eo[rr * 200 + cc]);
                    s_xo[rr * 200 + cc + 1] = elu1(sum2(a1[j]) + s_eo[rr * 200 + cc + 1]);
                }
            }
        }
        __syncthreads();

        // ====== P5: heads (2 s-cols x 4 rows) + action prefetch =============
        if (tid < 120) {
            const int rh = tid / 60;
            const int rem = tid - rh * 60;
            const int h = rem / 15, s2 = rem % 15;
            const float* src = ((h < 2) ? s_xo : s_x) + rh * 4 * 200;
            const float4* wp = g_h8 + (h * 750 + s2) * 2;
            ull a0[4], a1[4];
#pragma unroll
            for (int j = 0; j < 4; j++) { a0[j] = 0; a1[j] = 0; }
#pragma unroll 2
            for (int kq = 0; kq < 50; kq++) {
                ulonglong2 w0 = ldg2(wp + kq * 30);
                ulonglong2 w1 = ldg2(wp + kq * 30 + 1);
#pragma unroll
                for (int j = 0; j < 4; j++) {
                    ulonglong2 v = lds2(src + j * 200 + 4 * kq);
                    a0[j] = fma2(v.x, w0.x, a0[j]);
                    a0[j] = fma2(v.y, w0.y, a0[j]);
                    a1[j] = fma2(v.x, w1.x, a1[j]);
                    a1[j] = fma2(v.y, w1.y, a1[j]);
                }
            }
            int s0 = 2 * s2;
            float hb0 = s_hb[h * 30 + s0], hb1 = s_hb[h * 30 + s0 + 1];
#pragma unroll
            for (int j = 0; j < 4; j++) {
                int rr = rh * 4 + j;
                float* orow = out + ((size_t)(b0 + rr) * TLEN + t) * 580;
#pragma unroll
                for (int q = 0; q < 2; q++) {
                    float v = sum2(q == 0 ? a0[j] : a1[j]) + (q == 0 ? hb0 : hb1);
                    int s = s0 + q;
                    float res;
                    if (h == 0)      { res = v;                   orow[s]       = res; }
                    else if (h == 1) { res = softplus1(v);        orow[30 + s]  = res; }
                    else if (h == 2) { res = v;                   orow[290 + s] = res; }
                    else             { res = softplus1(v) + 0.1f; orow[320 + s] = res; }
                    s_hd[h * 240 + rr * 30 + s] = res;
                }
            }
        } else if (tid >= 640 && tid < 688 && t + 1 < TLEN) {
            int idx = tid - 640;
            int r = idx / 6, j = idx % 6;
            s_in[r * 40 + 30 + j] =
                action[(size_t)(b0 + r) * (TLEN * ADIM) + (t + 1) * ADIM + j];
        }
        __syncthreads();

        // ====== P6: samples + stoch carry ===================================
        if (tid < 240) {
            int r = tid / 30, s = tid - r * 30;
            size_t nidx = (size_t)t * (BSZ * SDIM) + (size_t)(b0 + r) * SDIM + s;
            float om  = s_hd[r * 30 + s];
            float osd = s_hd[240 + r * 30 + s];
            float ost = om + osd * __ldg(&noise_post[nidx]);
            float pm  = s_hd[480 + r * 30 + s];
            float psd = s_hd[720 + r * 30 + s];
            float pst = pm + psd * __ldg(&noise_prior[nidx]);
            float* orow = out + ((size_t)(b0 + r) * TLEN + t) * 580;
            orow[60 + s]  = ost;
            orow[350 + s] = pst;
            s_in[r * 40 + s] = ost;
        }

        { float* tmp = pd; pd = pn; pn = tmp; }
        __syncthreads();
    }
}

// ---------------------------------------------------------------------------
// Launch
// ---------------------------------------------------------------------------
extern "C" void kernel_launch(void* const* d_in, const int* in_sizes, int n_in,
                              void* d_out, int out_size) {
    const float* embed       = (const float*)d_in[0];
    const float* action      = (const float*)d_in[1];
    const float* noise_prior = (const float*)d_in[2];
    const float* noise_post  = (const float*)d_in[3];
    const float* w_img1      = (const float*)d_in[4];
    const float* b_img1      = (const float*)d_in[5];
    const float* gru_w       = (const float*)d_in[6];
    const float* gru_u       = (const float*)d_in[7];
    const float* gru_b       = (const float*)d_in[8];
    const float* gru_rb      = (const float*)d_in[9];
    const float* w_img2      = (const float*)d_in[10];
    const float* b_img2      = (const float*)d_in[11];
    const float* w_imean     = (const float*)d_in[12];
    const float* b_imean     = (const float*)d_in[13];
    const float* w_istd      = (const float*)d_in[14];
    const float* b_istd      = (const float*)d_in[15];
    const float* w_obs1      = (const float*)d_in[16];
    const float* b_obs1      = (const float*)d_in[17];
    const float* w_omean     = (const float*)d_in[18];
    const float* b_omean     = (const float*)d_in[19];
    const float* w_ostd      = (const float*)d_in[20];
    const float* b_ostd      = (const float*)d_in[21];
    float* out = (float*)d_out;

    eo_gemm_kernel<<<BSZ * TLEN / 64, 320>>>(embed, w_obs1, b_obs1,
                                             w_img1, gru_w, gru_u, w_img2,
                                             w_omean, w_ostd, w_imean, w_istd);
    rssm_recur_kernel<<<BSZ / 8, 800>>>(action, noise_prior, noise_post,
                                        b_img1, gru_b, gru_rb, b_img2,
                                        b_imean, b_istd, b_omean, b_ostd, out);
}

// round 5
// speedup vs baseline: 1.3367x; 1.3367x over previous
#include <cuda_runtime.h>

#define BSZ   1024
#define TLEN  64
#define SDIM  30
#define DDIM  200
#define HDIM  200
#define EDIM  1024
#define ADIM  6

typedef unsigned long long ull;

// ---------------------------------------------------------------------------
// Device scratch
// ---------------------------------------------------------------------------
__device__ float g_eo[(size_t)BSZ * TLEN * HDIM];   // embed @ w_obs1[200:] + b_obs1

// k-quad packed weights (float4 = 4 consecutive k values for one output col)
__device__ float4 g_gru4[6 * 50 * 200];  // [st][kq][c]; st: Wz,Wr,Wh,Uz,Ur,Uh
__device__ float4 g_p4[2 * 50 * 200];    // [mat][kq][c]; mat: img2, obs1d
__device__ float4 g_i14[9 * 200];        // img1 [kq][c], K=36
__device__ float4 g_h4[4 * 50 * 30];     // heads [h][kq][s]

// ---------------------------------------------------------------------------
// Helpers
// ---------------------------------------------------------------------------
__device__ __forceinline__ ull fma2(ull a, ull b, ull c) {
    ull d;
    asm("fma.rn.f32x2 %0, %1, %2, %3;" : "=l"(d) : "l"(a), "l"(b), "l"(c));
    return d;
}
__device__ __forceinline__ float sum2(ull a) {
    float2 f;
    asm("mov.b64 {%0, %1}, %2;" : "=f"(f.x), "=f"(f.y) : "l"(a));
    return f.x + f.y;
}
__device__ __forceinline__ ulonglong2 ldg2(const float4* p) {
    return __ldg(reinterpret_cast<const ulonglong2*>(p));
}
__device__ __forceinline__ ulonglong2 lds2(const float* p) {
    return *reinterpret_cast<const ulonglong2*>(p);
}
__device__ __forceinline__ float elu1(float v) {
    return v > 0.f ? v : (__expf(v) - 1.f);
}
__device__ __forceinline__ float softplus1(float x) {
    return fmaxf(x, 0.f) + log1pf(__expf(-fabsf(x)));
}
__device__ __forceinline__ float sigmoid1(float x) {
    return 1.f / (1.f + __expf(-x));
}

// ---------------------------------------------------------------------------
// Repack: k-quad layouts (one float per index i)
// ---------------------------------------------------------------------------
__device__ __forceinline__ void repack_one(int i,
                                           const float* __restrict__ w_img1,
                                           const float* __restrict__ gru_w,
                                           const float* __restrict__ gru_u,
                                           const float* __restrict__ w_img2,
                                           const float* __restrict__ w_obs1,
                                           const float* __restrict__ w_omean,
                                           const float* __restrict__ w_ostd,
                                           const float* __restrict__ w_imean,
                                           const float* __restrict__ w_istd) {
    if (i < 240000) {                       // GRU 6 streams
        int f = i & 3, q = i >> 2;
        int st = q / 10000, rem = q % 10000, kq = rem / 200, cc = rem % 200;
        int k = 4 * kq + f;
        float v = (st < 3) ? gru_w[k * 600 + st * 200 + cc]
                           : gru_u[k * 600 + (st - 3) * 200 + cc];
        ((float*)g_gru4)[i] = v;
    } else if (i < 320000) {                // img2 / obs1d
        int j = i - 240000;
        int f = j & 3, q = j >> 2;
        int mat = q / 10000, rem = q % 10000, kq = rem / 200, cc = rem % 200;
        int k = 4 * kq + f;
        ((float*)g_p4)[j] = (mat == 0) ? w_img2[k * 200 + cc] : w_obs1[k * 200 + cc];
    } else if (i < 327200) {                // img1
        int j = i - 320000;
        int f = j & 3, q = j >> 2;
        int kq = q / 200, cc = q % 200;
        int k = 4 * kq + f;                 // k < 36 always
        ((float*)g_i14)[j] = w_img1[k * 200 + cc];
    } else if (i < 351200) {                // heads
        int j = i - 327200;
        int f = j & 3, q = j >> 2;
        int h = q / 1500, rem = q % 1500, kq = rem / 30, s = rem % 30;
        int k = 4 * kq + f;
        const float* src = (h == 0) ? w_omean : (h == 1) ? w_ostd
                         : (h == 2) ? w_imean : w_istd;
        ((float*)g_h4)[j] = src[k * 30 + s];
    }
}

// ---------------------------------------------------------------------------
// Kernel 1: repack + eo GEMM (register double-buffered prefetch)
// ---------------------------------------------------------------------------
__global__ __launch_bounds__(320, 1)
void eo_gemm_kernel(const float* __restrict__ embed,
                    const float* __restrict__ w_obs1,
                    const float* __restrict__ b_obs1,
                    const float* __restrict__ w_img1,
                    const float* __restrict__ gru_w,
                    const float* __restrict__ gru_u,
                    const float* __restrict__ w_img2,
                    const float* __restrict__ w_omean,
                    const float* __restrict__ w_ostd,
                    const float* __restrict__ w_imean,
                    const float* __restrict__ w_istd) {
    for (int i = blockIdx.x * 320 + threadIdx.x; i < 351200; i += 1024 * 320) {
        repack_one(i, w_img1, gru_w, gru_u, w_img2, w_obs1,
                   w_omean, w_ostd, w_imean, w_istd);
    }

    __shared__ __align__(16) float as_f[64 * 32];
    __shared__ __align__(16) float ws_f[32 * 200];
    const ull* as_u = (const ull*)as_f;
    const ull* ws_u = (const ull*)ws_f;

    const int tid = threadIdx.x;
    const int tx = tid % 40;
    const int ty = tid / 40;
    const int m0 = blockIdx.x * 64;

    ull acc[8][5];
#pragma unroll
    for (int r = 0; r < 8; r++)
#pragma unroll
        for (int j = 0; j < 5; j++) acc[r][j] = 0ull;

    float4 aP[2];
    float4 wP[5];
    const bool aPred = (tid < 256);

    {
        if (aPred) {
#pragma unroll
            for (int p = 0; p < 2; p++) {
                int q = tid + 256 * p;
                int r = q >> 3, qq = q & 7;
                aP[p] = *reinterpret_cast<const float4*>(
                    embed + (size_t)(m0 + r) * 1024 + qq * 4);
            }
        }
#pragma unroll
        for (int p = 0; p < 5; p++) {
            int q = tid + 320 * p;
            int k = q / 50, c4 = (q % 50) * 4;
            wP[p] = *reinterpret_cast<const float4*>(
                w_obs1 + (size_t)(200 + k) * 200 + c4);
        }
    }

    for (int chunk = 0; chunk < 32; chunk++) {
        __syncthreads();
        if (aPred) {
#pragma unroll
            for (int p = 0; p < 2; p++) {
                int q = tid + 256 * p;
                int r = q >> 3, qq = q & 7;
                *reinterpret_cast<float4*>(as_f + r * 32 + qq * 4) = aP[p];
            }
        }
#pragma unroll
        for (int p = 0; p < 5; p++) {
            int q = tid + 320 * p;
            int k = q / 50, c4 = (q % 50) * 4;
            float vv[4] = {wP[p].x, wP[p].y, wP[p].z, wP[p].w};
#pragma unroll
            for (int j = 0; j < 4; j++)
                ws_f[((k >> 1) * 200 + c4 + j) * 2 + (k & 1)] = vv[j];
        }
        __syncthreads();

        if (chunk < 31) {
            int k0 = (chunk + 1) * 32;
            if (aPred) {
#pragma unroll
                for (int p = 0; p < 2; p++) {
                    int q = tid + 256 * p;
                    int r = q >> 3, qq = q & 7;
                    aP[p] = *reinterpret_cast<const float4*>(
                        embed + (size_t)(m0 + r) * 1024 + k0 + qq * 4);
                }
            }
#pragma unroll
            for (int p = 0; p < 5; p++) {
                int q = tid + 320 * p;
                int k = q / 50, c4 = (q % 50) * 4;
                wP[p] = *reinterpret_cast<const float4*>(
                    w_obs1 + (size_t)(200 + k0 + k) * 200 + c4);
            }
        }

#pragma unroll
        for (int kp = 0; kp < 16; kp++) {
            ull wv[5];
#pragma unroll
            for (int j = 0; j < 5; j++) wv[j] = ws_u[kp * 200 + tx * 5 + j];
#pragma unroll
            for (int r = 0; r < 8; r++) {
                ull av = as_u[(ty * 8 + r) * 16 + kp];
#pragma unroll
                for (int j = 0; j < 5; j++) acc[r][j] = fma2(av, wv[j], acc[r][j]);
            }
        }
    }

#pragma unroll
    for (int r = 0; r < 8; r++) {
        int m = m0 + ty * 8 + r;
#pragma unroll
        for (int j = 0; j < 5; j++) {
            int cc = tx * 5 + j;
            g_eo[(size_t)m * 200 + cc] = sum2(acc[r][j]) + b_obs1[cc];
        }
    }
}

// ---------------------------------------------------------------------------
// Kernel 2: persistent recurrent kernel.
// 128 CTAs x 8 rows, 800 threads.
// P2 mapping: tid -> (c, rh, side): side 0 computes x@{Wz,Wr,Wh},
// side 1 computes d@{Uz,Ur,Uh}; each thread: 3 streams x 1 col x 4 rows.
// ---------------------------------------------------------------------------
__global__ __launch_bounds__(800, 1)
void rssm_recur_kernel(const float* __restrict__ action,
                       const float* __restrict__ noise_prior,
                       const float* __restrict__ noise_post,
                       const float* __restrict__ b_img1,
                       const float* __restrict__ gru_b,
                       const float* __restrict__ gru_rb,
                       const float* __restrict__ b_img2,
                       const float* __restrict__ b_imean,
                       const float* __restrict__ b_istd,
                       const float* __restrict__ b_omean,
                       const float* __restrict__ b_ostd,
                       float* __restrict__ out) {
    __shared__ __align__(16) float sm[20608];
    float* s_in = sm;            // [8][40]                                320
    float* det0 = sm + 320;      // [8][200]                              1600
    float* det1 = sm + 1920;     // [8][200]                              1600
    float* s_x  = sm + 3520;     // [8][200]  img1 out, later x2          1600
    float* s_xo = sm + 5120;     // [8][200]                              1600
    float* s_eo = sm + 6720;     // [8][200]                              1600
    float* s_hd = sm + 8320;     // [4][8][30]                             960
    float* s_g  = sm + 9280;     // [6][8][200] GRU stream partials       9600
    float* s_b1 = sm + 18880;    // [200]
    float* s_b2 = sm + 19080;    // [200]
    float* s_gb = sm + 19280;    // [6][200]
    float* s_hb = sm + 20480;    // [4][30]

    const int tid = threadIdx.x;
    const int b0 = blockIdx.x * 8;

    // ---- P2 mapping ----
    const int cP  = tid % 200;
    const int grp = tid / 200;           // 0..3
    const int rhP = grp & 1;             // row half
    const int sgP = grp >> 1;            // 0: x-side, 1: d-side
    const float4* wpP2 = g_gru4 + sgP * 30000 + cP;

    // ---- P4 mapping ----
    const int matP4 = tid / 400;
    const int cP4   = tid % 200;
    const int rhP4  = (tid / 200) & 1;
    const float4* wpP4 = g_p4 + matP4 * 10000 + cP4;

    // ---- P5 mapping (tid < 480) ----
    const int hP5 = tid / 120;
    const int remP5 = tid % 120;
    const int sP5 = remP5 % 30;
    const int rqP5 = remP5 / 30;         // 2 rows: 2*rq, 2*rq+1

    // ---- init: biases to smem, carry zeros, action[0] ----
    if (tid < 200) {
        s_b1[tid] = b_img1[tid];
        s_b2[tid] = b_img2[tid];
    }
    for (int i = tid; i < 1200; i += 800) {
        int st = i / 200, cc = i % 200;
        s_gb[i] = (st < 3) ? gru_b[st * 200 + cc] : gru_rb[(st - 3) * 200 + cc];
    }
    if (tid < 120) {
        int h = tid / 30, s = tid % 30;
        s_hb[tid] = (h == 0) ? b_omean[s] : (h == 1) ? b_ostd[s]
                  : (h == 2) ? b_imean[s] : b_istd[s];
    }
    for (int i = tid; i < 320; i += 800) s_in[i] = 0.f;
    for (int i = tid; i < 1600; i += 800) det0[i] = 0.f;
    if (tid < 48) {
        int r = tid / 6, j = tid % 6;
        s_in[r * 40 + 30 + j] = action[(size_t)(b0 + r) * (TLEN * ADIM) + j];
    }
    float* pd = det0;
    float* pn = det1;
    __syncthreads();

    for (int t = 0; t < TLEN; ++t) {
        // ====== P1: x = elu([stoch,action]@W1 + b)  |  eo loads =============
        if (tid < 400) {
            const int c = tid % 200, rh = tid / 200;
            ull acc[4];
#pragma unroll
            for (int j = 0; j < 4; j++) acc[j] = 0ull;
#pragma unroll
            for (int kq = 0; kq < 9; kq++) {
                ulonglong2 w = ldg2(g_i14 + kq * 200 + c);
#pragma unroll
                for (int j = 0; j < 4; j++) {
                    ulonglong2 v = lds2(s_in + (rh * 4 + j) * 40 + 4 * kq);
                    acc[j] = fma2(v.x, w.x, acc[j]);
                    acc[j] = fma2(v.y, w.y, acc[j]);
                }
            }
            float bb = s_b1[c];
#pragma unroll
            for (int j = 0; j < 4; j++)
                s_x[(rh * 4 + j) * 200 + c] = elu1(sum2(acc[j]) + bb);
        } else if (tid >= 600) {
            int t2 = tid - 600;
#pragma unroll
            for (int i = 0; i < 8; i++) {
                int e = t2 + 200 * i;
                int r = e / 200, cc = e - r * 200;
                s_eo[e] = __ldg(&g_eo[((size_t)(b0 + r) * TLEN + t) * 200 + cc]);
            }
        }
        __syncthreads();

        // ====== P2: 3 streams x 1 col x 4 rows per thread ===================
        {
            const float* src = sgP ? pd : s_x;
            const float* srb = src + rhP * 4 * 200;
            ull a0[4], a1[4], a2[4];
#pragma unroll
            for (int j = 0; j < 4; j++) { a0[j] = 0; a1[j] = 0; a2[j] = 0; }
            ulonglong2 w0 = ldg2(wpP2);
            ulonglong2 w1 = ldg2(wpP2 + 10000);
            ulonglong2 w2 = ldg2(wpP2 + 20000);
            for (int kq = 0; kq < 50; kq++) {
                const int kn = (kq < 49) ? kq + 1 : 49;
                ulonglong2 n0 = ldg2(wpP2 + kn * 200);
                ulonglong2 n1 = ldg2(wpP2 + 10000 + kn * 200);
                ulonglong2 n2 = ldg2(wpP2 + 20000 + kn * 200);
#pragma unroll
                for (int j = 0; j < 4; j++) {
                    ulonglong2 v = lds2(srb + j * 200 + 4 * kq);
                    a0[j] = fma2(v.x, w0.x, a0[j]);
                    a0[j] = fma2(v.y, w0.y, a0[j]);
                    a1[j] = fma2(v.x, w1.x, a1[j]);
                    a1[j] = fma2(v.y, w1.y, a1[j]);
                    a2[j] = fma2(v.x, w2.x, a2[j]);
                    a2[j] = fma2(v.y, w2.y, a2[j]);
                }
                w0 = n0; w1 = n1; w2 = n2;
            }
            const int stb = sgP * 3;
#pragma unroll
            for (int j = 0; j < 4; j++) {
                int row = rhP * 4 + j;
                s_g[(stb + 0) * 1600 + row * 200 + cP] = sum2(a0[j]) + s_gb[(stb + 0) * 200 + cP];
                s_g[(stb + 1) * 1600 + row * 200 + cP] = sum2(a1[j]) + s_gb[(stb + 1) * 200 + cP];
                s_g[(stb + 2) * 1600 + row * 200 + cP] = sum2(a2[j]) + s_gb[(stb + 2) * 200 + cP];
            }
        }
        __syncthreads();

        // ====== P3: gates, deter_n ==========================================
#pragma unroll
        for (int i = 0; i < 2; i++) {
            int idx = tid + 800 * i;
            float z  = sigmoid1(s_g[idx] + s_g[4800 + idx]);
            float rg = sigmoid1(s_g[1600 + idx] + s_g[6400 + idx]);
            float a  = s_g[3200 + idx] + rg * s_g[8000 + idx];
            float e2 = __expf(2.f * a);
            float th = 1.f - 2.f / (e2 + 1.f);
            float dn = z * pd[idx] + (1.f - z) * th;
            pn[idx] = dn;
            int r = idx / 200, cc = idx - r * 200;
            float* orow = out + ((size_t)(b0 + r) * TLEN + t) * 580;
            orow[90 + cc]  = dn;
            orow[380 + cc] = dn;
        }
        __syncthreads();

        // ====== P4: x2 / xo, 1 col x 4 rows per thread, all 800 =============
        {
            const float* db = pn + rhP4 * 4 * 200;
            ull acc[4];
#pragma unroll
            for (int j = 0; j < 4; j++) acc[j] = 0ull;
            ulonglong2 w = ldg2(wpP4);
            for (int kq = 0; kq < 50; kq++) {
                const int kn = (kq < 49) ? kq + 1 : 49;
                ulonglong2 n = ldg2(wpP4 + kn * 200);
#pragma unroll
                for (int j = 0; j < 4; j++) {
                    ulonglong2 v = lds2(db + j * 200 + 4 * kq);
                    acc[j] = fma2(v.x, w.x, acc[j]);
                    acc[j] = fma2(v.y, w.y, acc[j]);
                }
                w = n;
            }
            if (matP4 == 0) {
                float bb = s_b2[cP4];
#pragma unroll
                for (int j = 0; j < 4; j++) {
                    int row = rhP4 * 4 + j;
                    s_x[row * 200 + cP4] = elu1(sum2(acc[j]) + bb);
                }
            } else {
#pragma unroll
                for (int j = 0; j < 4; j++) {
                    int row = rhP4 * 4 + j;
                    s_xo[row * 200 + cP4] = elu1(sum2(acc[j]) + s_eo[row * 200 + cP4]);
                }
            }
        }
        __syncthreads();

        // ====== P5: heads (1 s-col x 2 rows) + action prefetch ==============
        if (tid < 480) {
            const float* src = ((hP5 < 2) ? s_xo : s_x) + rqP5 * 2 * 200;
            const float4* wp = g_h4 + hP5 * 1500 + sP5;
            ull a0 = 0ull, a1 = 0ull;
            ulonglong2 w = ldg2(wp);
            for (int kq = 0; kq < 50; kq++) {
                const int kn = (kq < 49) ? kq + 1 : 49;
                ulonglong2 n = ldg2(wp + kn * 30);
                ulonglong2 v0 = lds2(src + 4 * kq);
                a0 = fma2(v0.x, w.x, a0);
                a0 = fma2(v0.y, w.y, a0);
                ulonglong2 v1 = lds2(src + 200 + 4 * kq);
                a1 = fma2(v1.x, w.x, a1);
                a1 = fma2(v1.y, w.y, a1);
                w = n;
            }
            float hb = s_hb[hP5 * 30 + sP5];
#pragma unroll
            for (int j = 0; j < 2; j++) {
                int rr = rqP5 * 2 + j;
                float v = sum2(j == 0 ? a0 : a1) + hb;
                float* orow = out + ((size_t)(b0 + rr) * TLEN + t) * 580;
                float res;
                if (hP5 == 0)      { res = v;                   orow[sP5]       = res; }
                else if (hP5 == 1) { res = softplus1(v);        orow[30 + sP5]  = res; }
                else if (hP5 == 2) { res = v;                   orow[290 + sP5] = res; }
                else               { res = softplus1(v) + 0.1f; orow[320 + sP5] = res; }
                s_hd[hP5 * 240 + rr * 30 + sP5] = res;
            }
        } else if (tid >= 480 && tid < 528 && t + 1 < TLEN) {
            int idx = tid - 480;
            int r = idx / 6, j = idx % 6;
            s_in[r * 40 + 30 + j] =
                action[(size_t)(b0 + r) * (TLEN * ADIM) + (t + 1) * ADIM + j];
        }
        __syncthreads();

        // ====== P6: samples + stoch carry ===================================
        if (tid < 240) {
            int r = tid / 30, s = tid - r * 30;
            size_t nidx = (size_t)t * (BSZ * SDIM) + (size_t)(b0 + r) * SDIM + s;
            float om  = s_hd[r * 30 + s];
            float osd = s_hd[240 + r * 30 + s];
            float ost = om + osd * __ldg(&noise_post[nidx]);
            float pm  = s_hd[480 + r * 30 + s];
            float psd = s_hd[720 + r * 30 + s];
            float pst = pm + psd * __ldg(&noise_prior[nidx]);
            float* orow = out + ((size_t)(b0 + r) * TLEN + t) * 580;
            orow[60 + s]  = ost;
            orow[350 + s] = pst;
            s_in[r * 40 + s] = ost;
        }

        { float* tmp = pd; pd = pn; pn = tmp; }
        __syncthreads();
    }
}

// ---------------------------------------------------------------------------
// Launch
// ---------------------------------------------------------------------------
extern "C" void kernel_launch(void* const* d_in, const int* in_sizes, int n_in,
                              void* d_out, int out_size) {
    const float* embed       = (const float*)d_in[0];
    const float* action      = (const float*)d_in[1];
    const float* noise_prior = (const float*)d_in[2];
    const float* noise_post  = (const float*)d_in[3];
    const float* w_img1      = (const float*)d_in[4];
    const float* b_img1      = (const float*)d_in[5];
    const float* gru_w       = (const float*)d_in[6];
    const float* gru_u       = (const float*)d_in[7];
    const float* gru_b       = (const float*)d_in[8];
    const float* gru_rb      = (const float*)d_in[9];
    const float* w_img2      = (const float*)d_in[10];
    const float* b_img2      = (const float*)d_in[11];
    const float* w_imean     = (const float*)d_in[12];
    const float* b_imean     = (const float*)d_in[13];
    const float* w_istd      = (const float*)d_in[14];
    const float* b_istd      = (const float*)d_in[15];
    const float* w_obs1      = (const float*)d_in[16];
    const float* b_obs1      = (const float*)d_in[17];
    const float* w_omean     = (const float*)d_in[18];
    const float* b_omean     = (const float*)d_in[19];
    const float* w_ostd      = (const float*)d_in[20];
    const float* b_ostd      = (const float*)d_in[21];
    float* out = (float*)d_out;

    eo_gemm_kernel<<<BSZ * TLEN / 64, 320>>>(embed, w_obs1, b_obs1,
                                             w_img1, gru_w, gru_u, w_img2,
                                             w_omean, w_ostd, w_imean, w_istd);
    rssm_recur_kernel<<<BSZ / 8, 800>>>(action, noise_prior, noise_post,
                                        b_img1, gru_b, gru_rb, b_img2,
                                        b_imean, b_istd, b_omean, b_ostd, out);
}